// round 4
// baseline (speedup 1.0000x reference)
#include <cuda_runtime.h>
#include <cuda_bf16.h>

// Fixed problem shapes
#define HH 512
#define WW 640
#define RAD 4             // K=9 -> R=4
#define EPS_C 0.5f

// Census tile config: 32x8 threads, 4 pixels per thread -> 128x8 pixel tile
#define BXT 32
#define BYT 8
#define PX  4
#define TILE_W (BXT*PX)         // 128
#define TW (TILE_W + 2*RAD)     // 136 floats per halo row
#define TH (BYT + RAD)          // 12 halo rows (dh >= 0 only)
#define NTHREADS (BXT*BYT)      // 256

__device__ double g_acc;

__global__ void init_kernel() { g_acc = 0.0; }

// ---------------------------------------------------------------------------
// Packed f32x2 helpers (sm_100a)
// ---------------------------------------------------------------------------
union PU { float2 f; unsigned long long u; };

__device__ __forceinline__ float2 padd(float2 a, float2 b) {
    PU x, y, r; x.f = a; y.f = b;
    asm("add.rn.f32x2 %0,%1,%2;" : "=l"(r.u) : "l"(x.u), "l"(y.u));
    return r.f;
}
__device__ __forceinline__ float2 psub(float2 a, float2 b) {
    PU x, y, r; x.f = a; y.f = b;
    asm("sub.rn.f32x2 %0,%1,%2;" : "=l"(r.u) : "l"(x.u), "l"(y.u));
    return r.f;
}
__device__ __forceinline__ float2 pmul(float2 a, float2 b) {
    PU x, y, r; x.f = a; y.f = b;
    asm("mul.rn.f32x2 %0,%1,%2;" : "=l"(r.u) : "l"(x.u), "l"(y.u));
    return r.f;
}
__device__ __forceinline__ float2 pfma(float2 a, float2 b, float2 c) {
    PU x, y, z, r; x.f = a; y.f = b; z.f = c;
    asm("fma.rn.f32x2 %0,%1,%2,%3;" : "=l"(r.u) : "l"(x.u), "l"(y.u), "l"(z.u));
    return r.f;
}
__device__ __forceinline__ float2 pabs(float2 a) {
    PU x; x.f = a; x.u &= 0x7FFFFFFF7FFFFFFFULL; return x.f;
}
__device__ __forceinline__ float frcp(float x) {
    float r; asm("rcp.approx.ftz.f32 %0,%1;" : "=f"(r) : "f"(x)); return r;
}

// ---------------------------------------------------------------------------
// Census pair op: two pixel-pairs packed. Single reciprocal per pair:
//   |ca - cb| = |da*sb - db*sa| / (sa*sb),  sa = eps+|da|, sb = eps+|db|
// ---------------------------------------------------------------------------
template<bool CM>
__device__ __forceinline__ void census_pair(float2 na, float2 nb,
                                            float2 ac, float2 bc,
                                            float2 m, float2& acc)
{
    const float2 eps2 = {EPS_C, EPS_C};
    float2 da = psub(na, ac);
    float2 db = psub(nb, bc);
    float2 sa = padd(eps2, pabs(da));
    float2 sb = padd(eps2, pabs(db));
    float2 p  = pmul(da, sb);
    float2 q  = pmul(db, sa);
    float2 num = pabs(psub(p, q));
    float2 den = pmul(sa, sb);
    float2 r;
    r.x = frcp(den.x);
    r.y = frcp(den.y);
    if (CM) r = pmul(r, m);
    acc = pfma(num, r, acc);
}

// Process one dh row: neighbors for dw = JLO-4 .. 4, pixels px0..px3.
// E pairs from base arrays, O pairs from the 1-float-shifted copies.
template<int JLO, bool CM>
__device__ __forceinline__ void row_accum(
    const float* __restrict__ As_row, const float* __restrict__ A1_row,
    const float* __restrict__ Bs_row, const float* __restrict__ B1_row,
    int cb,
    float2 ac01, float2 ac23, float2 bc01, float2 bc23,
    const float2 (&m01)[9], const float2 (&m23)[9],
    float2& acc01, float2& acc23)
{
    const float4* pa  = (const float4*)(As_row + cb);
    const float4* pa1 = (const float4*)(A1_row + cb);
    const float4* pb  = (const float4*)(Bs_row + cb);
    const float4* pb1 = (const float4*)(B1_row + cb);

    float2 EA[6], OA[6], EB[6], OB[6];
    // Needed float4 index range: s01 = JLO..8, s23 = JLO+2..10
    //  E indices s/2 in [JLO/2 .. 5], O indices (s-1)/2 in [(JLO-1)/2 .. 4]
    constexpr int F4E_LO = (JLO == 5) ? 1 : 0;   // EA[3..5] -> float4 1,2
    constexpr int F4O_LO = (JLO == 5) ? 1 : 0;   // OA[2..4] -> float4 1,2
#pragma unroll
    for (int f = F4E_LO; f < 3; f++) {
        float4 va = pa[f]; EA[2*f] = make_float2(va.x, va.y); EA[2*f+1] = make_float2(va.z, va.w);
        float4 vb = pb[f]; EB[2*f] = make_float2(vb.x, vb.y); EB[2*f+1] = make_float2(vb.z, vb.w);
    }
#pragma unroll
    for (int f = F4O_LO; f < 3; f++) {
        float4 va = pa1[f]; OA[2*f] = make_float2(va.x, va.y); OA[2*f+1] = make_float2(va.z, va.w);
        float4 vb = pb1[f]; OB[2*f] = make_float2(vb.x, vb.y); OB[2*f+1] = make_float2(vb.z, vb.w);
    }

#pragma unroll
    for (int j = JLO; j < 9; j++) {
        const int s01 = j;
        const int s23 = j + 2;
        float2 na01 = (s01 & 1) ? OA[(s01-1) >> 1] : EA[s01 >> 1];
        float2 nb01 = (s01 & 1) ? OB[(s01-1) >> 1] : EB[s01 >> 1];
        float2 na23 = (s23 & 1) ? OA[(s23-1) >> 1] : EA[s23 >> 1];
        float2 nb23 = (s23 & 1) ? OB[(s23-1) >> 1] : EB[s23 >> 1];
        census_pair<CM>(na01, nb01, ac01, bc01, m01[j], acc01);
        census_pair<CM>(na23, nb23, ac23, bc23, m23[j], acc23);
    }
}

template<bool CM>
__device__ __forceinline__ float census_block(
    const float (&As)[TH][TW], const float (&A1)[TH][TW],
    const float (&Bs)[TH][TW], const float (&B1)[TH][TW],
    int gx, int gy, int ty, int cb)
{
    float2 ac01 = *(const float2*)&As[ty][cb + RAD];
    float2 ac23 = *(const float2*)&As[ty][cb + RAD + 2];
    float2 bc01 = *(const float2*)&Bs[ty][cb + RAD];
    float2 bc23 = *(const float2*)&Bs[ty][cb + RAD + 2];

    float2 m01[9], m23[9];
    if (CM) {
#pragma unroll
        for (int j = 0; j < 9; j++) {
            int dw = j - 4;
            m01[j].x = ((unsigned)(gx + dw)     < WW) ? 1.f : 0.f;
            m01[j].y = ((unsigned)(gx + 1 + dw) < WW) ? 1.f : 0.f;
            m23[j].x = ((unsigned)(gx + 2 + dw) < WW) ? 1.f : 0.f;
            m23[j].y = ((unsigned)(gx + 3 + dw) < WW) ? 1.f : 0.f;
        }
    }

    float2 acc01 = {0.f, 0.f}, acc23 = {0.f, 0.f};

    // dh = 0 (same row), dw = 1..4  => j = 5..8
    row_accum<5, CM>(As[ty], A1[ty], Bs[ty], B1[ty], cb,
                     ac01, ac23, bc01, bc23, m01, m23, acc01, acc23);

    int dhmax = HH - 1 - gy; if (dhmax > RAD) dhmax = RAD;
#pragma unroll 1
    for (int dh = 1; dh <= dhmax; dh++) {
        row_accum<0, CM>(As[ty+dh], A1[ty+dh], Bs[ty+dh], B1[ty+dh], cb,
                         ac01, ac23, bc01, bc23, m01, m23, acc01, acc23);
    }
    return (acc01.x + acc01.y) + (acc23.x + acc23.y);
}

// ---------------------------------------------------------------------------
// Fused kernel: bilinear disparity warp (computed during tile load, written to
// proj for owned pixels) + census-SAD half-space partial sums.
// ---------------------------------------------------------------------------
__global__ __launch_bounds__(NTHREADS)
void census_fused_kernel(const float* __restrict__ disp,
                         const float* __restrict__ im,
                         const float* __restrict__ pattern,
                         float* __restrict__ proj)
{
    __shared__ __align__(16) float As[TH][TW];
    __shared__ __align__(16) float A1[TH][TW];   // shifted: A1[r][c] = As[r][c+1]
    __shared__ __align__(16) float Bs[TH][TW];
    __shared__ __align__(16) float B1[TH][TW];

    int x0 = blockIdx.x * TILE_W;
    int y0 = blockIdx.y * BYT;
    size_t boff = (size_t)blockIdx.z * (HH * WW);
    const float* dp = disp + boff;
    const float* bp = im + boff;
    float* pj = proj + boff;
    int tid = threadIdx.y * BXT + threadIdx.x;

    for (int i = tid; i < TH * TW; i += NTHREADS) {
        int r = i / TW, c = i - r * TW;
        int gy = y0 + r;
        int gx = x0 + c - RAD;
        float av = 0.f, bv = 0.f;
        if (gy < HH && (unsigned)gx < WW) {
            int g = gy * WW + gx;
            bv = bp[g];
            float d = dp[g];
            float x = (float)gx - d;
            x = fminf(fmaxf(x, 0.0f), (float)(WW - 1));
            float xf = floorf(x);
            float w  = x - xf;
            int i0 = (int)xf;
            int i1 = min(i0 + 1, WW - 1);
            const float* prow = pattern + gy * WW;
            float g0 = __ldg(prow + i0);
            float g1 = __ldg(prow + i1);
            av = fmaf(w, g1 - g0, g0);
            // owned interior pixel -> write pattern_proj output
            if (r < BYT && c >= RAD && c < RAD + TILE_W) pj[g] = av;
        }
        As[r][c] = av;
        Bs[r][c] = bv;
        if (c) { A1[r][c-1] = av; B1[r][c-1] = bv; }
    }
    __syncthreads();

    int tx = threadIdx.x, ty = threadIdx.y;
    int cb = PX * tx;
    int gx = x0 + cb;
    int gy = y0 + ty;

    bool cm = (blockIdx.x == 0) || (blockIdx.x == gridDim.x - 1);
    float acc = cm ? census_block<true >(As, A1, Bs, B1, gx, gy, ty, cb)
                   : census_block<false>(As, A1, Bs, B1, gx, gy, ty, cb);

    // block reduce -> one double atomic per block
#pragma unroll
    for (int o = 16; o > 0; o >>= 1)
        acc += __shfl_down_sync(0xffffffffu, acc, o);

    __shared__ float warpsum[NTHREADS / 32];
    if ((tid & 31) == 0) warpsum[tid >> 5] = acc;
    __syncthreads();
    if (tid < (NTHREADS / 32)) {
        float s = warpsum[tid];
#pragma unroll
        for (int o = (NTHREADS / 64); o > 0; o >>= 1)
            s += __shfl_down_sync(0xffffffffu, s, o);
        if (tid == 0) atomicAdd(&g_acc, (double)s);
    }
}

// ---------------------------------------------------------------------------
// Finalize: val = 2 * g_acc / (81 * B*H*W)
// ---------------------------------------------------------------------------
__global__ void finalize_kernel(float* __restrict__ out, int lead, double inv_norm)
{
    float v = (float)(2.0 * g_acc * inv_norm);
    for (int i = threadIdx.x; i < lead; i += 32) out[i] = v;
}

extern "C" void kernel_launch(void* const* d_in, const int* in_sizes, int n_in,
                              void* d_out, int out_size)
{
    const float* disp    = (const float*)d_in[0];
    const float* im      = (const float*)d_in[1];
    const float* pattern = (const float*)d_in[2];
    float* out = (float*)d_out;

    int total = in_sizes[0];           // B*1*H*W
    int B = total / (HH * WW);
    int lead = out_size - total;       // scalar(s) precede pattern_proj
    float* proj = out + lead;

    init_kernel<<<1, 1>>>();

    dim3 grid(WW / TILE_W, HH / BYT, B);   // 5 x 64 x B
    dim3 blk(BXT, BYT);
    census_fused_kernel<<<grid, blk>>>(disp, im, pattern, proj);

    finalize_kernel<<<1, 32>>>(out, lead, 1.0 / (81.0 * (double)total));
}

// round 9
// speedup vs baseline: 1.1633x; 1.1633x over previous
#include <cuda_runtime.h>
#include <cuda_bf16.h>

// Fixed problem shapes
#define HH 512
#define WW 640
#define RAD 4             // K=9 -> R=4
#define EPS_C 0.5f

// Census tile config: 32x8 threads, 4 pixels per thread -> 128x8 pixel tile
#define BXT 32
#define BYT 8
#define PX  4
#define TILE_W (BXT*PX)         // 128
#define TW (TILE_W + 2*RAD)     // 136 floats per halo row
#define TH (BYT + RAD)          // 12 halo rows (dh >= 0 only)
#define NTHREADS (BXT*BYT)      // 256

__device__ double g_acc;

// ---------------------------------------------------------------------------
// Packed f32x2 helpers (sm_100a)
// ---------------------------------------------------------------------------
union PU { float2 f; unsigned long long u; };

__device__ __forceinline__ float2 padd(float2 a, float2 b) {
    PU x, y, r; x.f = a; y.f = b;
    asm("add.rn.f32x2 %0,%1,%2;" : "=l"(r.u) : "l"(x.u), "l"(y.u));
    return r.f;
}
__device__ __forceinline__ float2 psub(float2 a, float2 b) {
    PU x, y, r; x.f = a; y.f = b;
    asm("sub.rn.f32x2 %0,%1,%2;" : "=l"(r.u) : "l"(x.u), "l"(y.u));
    return r.f;
}
__device__ __forceinline__ float2 pmul(float2 a, float2 b) {
    PU x, y, r; x.f = a; y.f = b;
    asm("mul.rn.f32x2 %0,%1,%2;" : "=l"(r.u) : "l"(x.u), "l"(y.u));
    return r.f;
}
__device__ __forceinline__ float2 pfma(float2 a, float2 b, float2 c) {
    PU x, y, z, r; x.f = a; y.f = b; z.f = c;
    asm("fma.rn.f32x2 %0,%1,%2,%3;" : "=l"(r.u) : "l"(x.u), "l"(y.u), "l"(z.u));
    return r.f;
}
__device__ __forceinline__ float2 pabs(float2 a) {
    PU x; x.f = a; x.u &= 0x7FFFFFFF7FFFFFFFULL; return x.f;
}
__device__ __forceinline__ float frcp(float x) {
    float r; asm("rcp.approx.ftz.f32 %0,%1;" : "=f"(r) : "f"(x)); return r;
}

// ---------------------------------------------------------------------------
// Kernel 1: pattern_proj. One block per (row, batch); 160 threads, strided
// scalar accesses (proj base may be only 4B-aligned: out + lead).
// Also zeroes the global accumulator (block (0,0), thread 0).
// ---------------------------------------------------------------------------
#define PT (WW/4)   // 160 threads
__global__ __launch_bounds__(PT)
void proj_kernel(const float* __restrict__ disp,
                 const float* __restrict__ pattern,
                 float* __restrict__ proj)
{
    int v = blockIdx.x;
    int b = blockIdx.y;
    if (v == 0 && b == 0 && threadIdx.x == 0) g_acc = 0.0;

    size_t base = ((size_t)b * HH + v) * WW;
    const float* prow = pattern + v * WW;

#pragma unroll
    for (int k = 0; k < 4; k++) {
        int u = threadIdx.x + k * PT;            // coalesced 128B/warp
        float d = disp[base + u];
        float x = (float)u - d;
        x = fminf(fmaxf(x, 0.0f), (float)(WW - 1));
        float xf = floorf(x);
        float w  = x - xf;
        int i0 = (int)xf;
        int i1 = min(i0 + 1, WW - 1);
        float g0 = __ldg(prow + i0);
        float g1 = __ldg(prow + i1);
        proj[base + u] = fmaf(w, g1 - g0, g0);
    }
}

// ---------------------------------------------------------------------------
// Census pair op: two pixel-pairs packed, 8 packed FMA-pipe ops + 2 MUFU.
//   |ca - cb| = |da*sb - db*sa| / (sa*sb),  sa = eps+|da|, sb = eps+|db|
//   implemented with db_neg = -db so the subtraction fuses into an FMA.
// ---------------------------------------------------------------------------
template<bool CM>
__device__ __forceinline__ void census_pair(float2 na, float2 nb,
                                            float2 ac, float2 bc,
                                            float2 m, float2& acc)
{
    const float2 eps2 = {EPS_C, EPS_C};
    float2 da  = psub(na, ac);
    float2 dbn = psub(bc, nb);                 // -(nb - bc)
    float2 sa  = padd(eps2, pabs(da));
    float2 sb  = padd(eps2, pabs(dbn));        // |dbn| == |db|
    float2 qn  = pmul(dbn, sa);                // -db*sa
    float2 num = pabs(pfma(da, sb, qn));       // |da*sb - db*sa|
    float2 den = pmul(sa, sb);
    float2 r;
    r.x = frcp(den.x);
    r.y = frcp(den.y);
    if (CM) r = pmul(r, m);
    acc = pfma(num, r, acc);
}

// Process one dh row: neighbors for dw = JLO-4 .. 4, pixels px0..px3.
// E pairs from base arrays, O pairs from the 1-float-shifted copies.
template<int JLO, bool CM>
__device__ __forceinline__ void row_accum(
    const float* __restrict__ As_row, const float* __restrict__ A1_row,
    const float* __restrict__ Bs_row, const float* __restrict__ B1_row,
    int cb,
    float2 ac01, float2 ac23, float2 bc01, float2 bc23,
    const float2 (&m01)[9], const float2 (&m23)[9],
    float2& acc01, float2& acc23)
{
    const float4* pa  = (const float4*)(As_row + cb);
    const float4* pa1 = (const float4*)(A1_row + cb);
    const float4* pb  = (const float4*)(Bs_row + cb);
    const float4* pb1 = (const float4*)(B1_row + cb);

    float2 EA[6], OA[6], EB[6], OB[6];
    constexpr int F4_LO = (JLO == 5) ? 1 : 0;
#pragma unroll
    for (int f = F4_LO; f < 3; f++) {
        float4 va = pa[f];  EA[2*f] = make_float2(va.x, va.y); EA[2*f+1] = make_float2(va.z, va.w);
        float4 vb = pb[f];  EB[2*f] = make_float2(vb.x, vb.y); EB[2*f+1] = make_float2(vb.z, vb.w);
        float4 wa = pa1[f]; OA[2*f] = make_float2(wa.x, wa.y); OA[2*f+1] = make_float2(wa.z, wa.w);
        float4 wb = pb1[f]; OB[2*f] = make_float2(wb.x, wb.y); OB[2*f+1] = make_float2(wb.z, wb.w);
    }

#pragma unroll
    for (int j = JLO; j < 9; j++) {
        const int s01 = j;
        const int s23 = j + 2;
        float2 na01 = (s01 & 1) ? OA[(s01-1) >> 1] : EA[s01 >> 1];
        float2 nb01 = (s01 & 1) ? OB[(s01-1) >> 1] : EB[s01 >> 1];
        float2 na23 = (s23 & 1) ? OA[(s23-1) >> 1] : EA[s23 >> 1];
        float2 nb23 = (s23 & 1) ? OB[(s23-1) >> 1] : EB[s23 >> 1];
        census_pair<CM>(na01, nb01, ac01, bc01, m01[j], acc01);
        census_pair<CM>(na23, nb23, ac23, bc23, m23[j], acc23);
    }
}

template<bool CM, bool FULLH>
__device__ __forceinline__ float census_block(
    const float (&As)[TH][TW], const float (&A1)[TH][TW],
    const float (&Bs)[TH][TW], const float (&B1)[TH][TW],
    int gx, int gy, int ty, int cb)
{
    float2 ac01 = *(const float2*)&As[ty][cb + RAD];
    float2 ac23 = *(const float2*)&As[ty][cb + RAD + 2];
    float2 bc01 = *(const float2*)&Bs[ty][cb + RAD];
    float2 bc23 = *(const float2*)&Bs[ty][cb + RAD + 2];

    float2 m01[9], m23[9];
    if (CM) {
#pragma unroll
        for (int j = 0; j < 9; j++) {
            int dw = j - 4;
            m01[j].x = ((unsigned)(gx + dw)     < WW) ? 1.f : 0.f;
            m01[j].y = ((unsigned)(gx + 1 + dw) < WW) ? 1.f : 0.f;
            m23[j].x = ((unsigned)(gx + 2 + dw) < WW) ? 1.f : 0.f;
            m23[j].y = ((unsigned)(gx + 3 + dw) < WW) ? 1.f : 0.f;
        }
    }

    float2 acc01 = {0.f, 0.f}, acc23 = {0.f, 0.f};

    // dh = 0 (same row), dw = 1..4  => j = 5..8
    row_accum<5, CM>(As[ty], A1[ty], Bs[ty], B1[ty], cb,
                     ac01, ac23, bc01, bc23, m01, m23, acc01, acc23);

    if (FULLH) {
#pragma unroll
        for (int dh = 1; dh <= RAD; dh++) {
            row_accum<0, CM>(As[ty+dh], A1[ty+dh], Bs[ty+dh], B1[ty+dh], cb,
                             ac01, ac23, bc01, bc23, m01, m23, acc01, acc23);
        }
    } else {
        int dhmax = HH - 1 - gy; if (dhmax > RAD) dhmax = RAD;
#pragma unroll 1
        for (int dh = 1; dh <= dhmax; dh++) {
            row_accum<0, CM>(As[ty+dh], A1[ty+dh], Bs[ty+dh], B1[ty+dh], cb,
                             ac01, ac23, bc01, bc23, m01, m23, acc01, acc23);
        }
    }
    return (acc01.x + acc01.y) + (acc23.x + acc23.y);
}

// ---------------------------------------------------------------------------
// Kernel 2: census-SAD over half-space offsets (dh>0, or dh==0 && dw>0);
// each unordered pair counted once, doubled in finalize.
// ---------------------------------------------------------------------------
__global__ __launch_bounds__(NTHREADS)
void census_kernel(const float* __restrict__ a_g,   // pattern_proj
                   const float* __restrict__ b_g)   // im
{
    __shared__ __align__(16) float As[TH][TW];
    __shared__ __align__(16) float A1[TH][TW];   // shifted: A1[r][c] = As[r][c+1]
    __shared__ __align__(16) float Bs[TH][TW];
    __shared__ __align__(16) float B1[TH][TW];

    int x0 = blockIdx.x * TILE_W;
    int y0 = blockIdx.y * BYT;
    const float* ap = a_g + (size_t)blockIdx.z * (HH * WW);
    const float* bp = b_g + (size_t)blockIdx.z * (HH * WW);
    int tid = threadIdx.y * BXT + threadIdx.x;

    for (int i = tid; i < TH * TW; i += NTHREADS) {
        int r = i / TW, c = i - r * TW;
        int gy = y0 + r;
        int gx = x0 + c - RAD;
        float av = 0.f, bv = 0.f;
        if (gy < HH && (unsigned)gx < WW) {
            int g = gy * WW + gx;
            av = ap[g];
            bv = bp[g];
        }
        As[r][c] = av;
        Bs[r][c] = bv;
        if (c) { A1[r][c-1] = av; B1[r][c-1] = bv; }
    }
    __syncthreads();

    int tx = threadIdx.x, ty = threadIdx.y;
    int cb = PX * tx;
    int gx = x0 + cb;
    int gy = y0 + ty;

    bool cm = (blockIdx.x == 0) || (blockIdx.x == gridDim.x - 1);
    bool fullh = (blockIdx.y != gridDim.y - 1);

    float acc;
    if (fullh) {
        acc = cm ? census_block<true , true >(As, A1, Bs, B1, gx, gy, ty, cb)
                 : census_block<false, true >(As, A1, Bs, B1, gx, gy, ty, cb);
    } else {
        acc = cm ? census_block<true , false>(As, A1, Bs, B1, gx, gy, ty, cb)
                 : census_block<false, false>(As, A1, Bs, B1, gx, gy, ty, cb);
    }

    // block reduce -> one double atomic per block
#pragma unroll
    for (int o = 16; o > 0; o >>= 1)
        acc += __shfl_down_sync(0xffffffffu, acc, o);

    __shared__ float warpsum[NTHREADS / 32];
    if ((tid & 31) == 0) warpsum[tid >> 5] = acc;
    __syncthreads();
    if (tid < (NTHREADS / 32)) {
        float s = warpsum[tid];
#pragma unroll
        for (int o = (NTHREADS / 64); o > 0; o >>= 1)
            s += __shfl_down_sync(0xffffffffu, s, o);
        if (tid == 0) atomicAdd(&g_acc, (double)s);
    }
}

// ---------------------------------------------------------------------------
// Kernel 3: val = 2 * g_acc / (81 * B*H*W)
// ---------------------------------------------------------------------------
__global__ void finalize_kernel(float* __restrict__ out, int lead, double inv_norm)
{
    float v = (float)(2.0 * g_acc * inv_norm);
    for (int i = threadIdx.x; i < lead; i += 32) out[i] = v;
}

extern "C" void kernel_launch(void* const* d_in, const int* in_sizes, int n_in,
                              void* d_out, int out_size)
{
    const float* disp    = (const float*)d_in[0];
    const float* im      = (const float*)d_in[1];
    const float* pattern = (const float*)d_in[2];
    float* out = (float*)d_out;

    int total = in_sizes[0];           // B*1*H*W
    int B = total / (HH * WW);
    int lead = out_size - total;       // scalar(s) precede pattern_proj
    float* proj = out + lead;

    dim3 pgrid(HH, B);
    proj_kernel<<<pgrid, PT>>>(disp, pattern, proj);

    dim3 grid(WW / TILE_W, HH / BYT, B);   // 5 x 64 x B
    dim3 blk(BXT, BYT);
    census_kernel<<<grid, blk>>>(proj, im);

    finalize_kernel<<<1, 32>>>(out, lead, 1.0 / (81.0 * (double)total));
}

// round 11
// speedup vs baseline: 1.3344x; 1.1471x over previous
#include <cuda_runtime.h>
#include <cuda_bf16.h>
#include <cuda_fp16.h>

// Fixed problem shapes
#define HH 512
#define WW 640
#define RAD 4             // K=9 -> R=4

// Census tile config: 32x8 threads, 4 pixels per thread -> 128x8 pixel tile
#define BXT 32
#define BYT 8
#define PX  4
#define TILE_W (BXT*PX)         // 128
#define TW (TILE_W + 2*RAD)     // 136 halves per halo row
#define TH (BYT + RAD)          // 12 halo rows (dh >= 0 only)
#define NTHREADS (BXT*BYT)      // 256

__device__ double g_acc;

// ---------------------------------------------------------------------------
// Kernel 1: pattern_proj (fp32, unchanged from R9 pass). One block per
// (row, batch); 160 threads, strided scalar coalesced accesses
// (proj base is only 4B-aligned: out + lead).
// ---------------------------------------------------------------------------
#define PT (WW/4)   // 160 threads
__global__ __launch_bounds__(PT)
void proj_kernel(const float* __restrict__ disp,
                 const float* __restrict__ pattern,
                 float* __restrict__ proj)
{
    int v = blockIdx.x;
    int b = blockIdx.y;
    if (v == 0 && b == 0 && threadIdx.x == 0) g_acc = 0.0;

    size_t base = ((size_t)b * HH + v) * WW;
    const float* prow = pattern + v * WW;

#pragma unroll
    for (int k = 0; k < 4; k++) {
        int u = threadIdx.x + k * PT;            // coalesced 128B/warp
        float d = disp[base + u];
        float x = (float)u - d;
        x = fminf(fmaxf(x, 0.0f), (float)(WW - 1));
        float xf = floorf(x);
        float w  = x - xf;
        int i0 = (int)xf;
        int i1 = min(i0 + 1, WW - 1);
        float g0 = __ldg(prow + i0);
        float g1 = __ldg(prow + i1);
        proj[base + u] = fmaf(w, g1 - g0, g0);
    }
}

// ---------------------------------------------------------------------------
// half2 census pair: two pixel-pairs packed in one half2 lane.
//   |ca - cb| = |da*sb - db*sa| / (sa*sb),  sa = eps+|da|, sb = eps+|db|
//   db_neg = -(nb-bc) fuses the subtraction into the HFMA2.
// 8 HFMA2-class ops + 1 h2rcp (MUFU) + 3 ALU abs per 2 elements.
// ---------------------------------------------------------------------------
__device__ __forceinline__ __half2 u2h(unsigned int u) {
    return *reinterpret_cast<__half2*>(&u);
}

template<bool CM>
__device__ __forceinline__ void census_pair_h(unsigned int na_u, unsigned int nb_u,
                                              __half2 ac, __half2 bc,
                                              __half2 m, __half2& acc)
{
    const __half2 eps2 = __float2half2_rn(0.5f);
    __half2 na  = u2h(na_u);
    __half2 nb  = u2h(nb_u);
    __half2 da  = __hsub2(na, ac);
    __half2 dbn = __hsub2(bc, nb);                 // -(nb - bc)
    __half2 sa  = __hadd2(eps2, __habs2(da));
    __half2 sb  = __hadd2(eps2, __habs2(dbn));     // |dbn| == |db|
    __half2 qn  = __hmul2(dbn, sa);                // -db*sa
    __half2 num = __habs2(__hfma2(da, sb, qn));    // |da*sb - db*sa|
    __half2 den = __hmul2(sa, sb);
    __half2 r   = h2rcp(den);
    if (CM) r = __hmul2(r, m);
    acc = __hfma2(num, r, acc);
}

// Process one dh row: offsets dw = JLO-4 .. 4 for pixel pairs (0,1) and (2,3).
// Even-parity half2s come straight from 8B LDS; odd-parity via PRMT.
// Row accumulators are folded into fp32 per row (magnitude <= ~36 in fp16).
template<int JLO, bool CM>
__device__ __forceinline__ void row_accum_h(
    const __half* __restrict__ As_row, const __half* __restrict__ Bs_row,
    int cb,
    __half2 ac01, __half2 ac23, __half2 bc01, __half2 bc23,
    const __half2 (&m01)[9], const __half2 (&m23)[9],
    float2& af01, float2& af23)
{
    const uint2* pa = (const uint2*)(As_row + cb);  // 8B aligned (cb even, row 16B-mult)
    const uint2* pb = (const uint2*)(Bs_row + cb);

    unsigned int EA[6], EB[6], OA[5], OB[5];
    constexpr int F2_LO = (JLO == 5) ? 1 : 0;   // JLO=5 needs EA[2..5] only
    constexpr int OK_LO = (JLO == 5) ? 2 : 0;   // JLO=5 needs OA[2..4] only
#pragma unroll
    for (int f = F2_LO; f < 3; f++) {
        uint2 va = pa[f]; EA[2*f] = va.x; EA[2*f+1] = va.y;
        uint2 vb = pb[f]; EB[2*f] = vb.x; EB[2*f+1] = vb.y;
    }
#pragma unroll
    for (int k = OK_LO; k < 5; k++) {
        OA[k] = __byte_perm(EA[k], EA[k+1], 0x5432);
        OB[k] = __byte_perm(EB[k], EB[k+1], 0x5432);
    }

    __half2 acc01 = __float2half2_rn(0.f);
    __half2 acc23 = __float2half2_rn(0.f);

#pragma unroll
    for (int j = JLO; j < 9; j++) {
        unsigned int na01, nb01, na23, nb23;
        if (j & 1) {
            na01 = OA[(j-1) >> 1]; nb01 = OB[(j-1) >> 1];
            na23 = OA[(j+1) >> 1]; nb23 = OB[(j+1) >> 1];
        } else {
            na01 = EA[j >> 1];     nb01 = EB[j >> 1];
            na23 = EA[(j >> 1)+1]; nb23 = EB[(j >> 1)+1];
        }
        census_pair_h<CM>(na01, nb01, ac01, bc01, m01[j], acc01);
        census_pair_h<CM>(na23, nb23, ac23, bc23, m23[j], acc23);
    }

    af01.x += __low2float(acc01);  af01.y += __high2float(acc01);
    af23.x += __low2float(acc23);  af23.y += __high2float(acc23);
}

template<bool CM, bool FULLH>
__device__ __forceinline__ float census_block_h(
    const __half (&As)[TH][TW], const __half (&Bs)[TH][TW],
    int gx, int gy, int ty, int cb)
{
    __half2 ac01 = *(const __half2*)&As[ty][cb + RAD];
    __half2 ac23 = *(const __half2*)&As[ty][cb + RAD + 2];
    __half2 bc01 = *(const __half2*)&Bs[ty][cb + RAD];
    __half2 bc23 = *(const __half2*)&Bs[ty][cb + RAD + 2];

    __half2 m01[9], m23[9];
    if (CM) {
#pragma unroll
        for (int j = 0; j < 9; j++) {
            int dw = j - 4;
            m01[j] = __floats2half2_rn(
                ((unsigned)(gx + dw)     < WW) ? 1.f : 0.f,
                ((unsigned)(gx + 1 + dw) < WW) ? 1.f : 0.f);
            m23[j] = __floats2half2_rn(
                ((unsigned)(gx + 2 + dw) < WW) ? 1.f : 0.f,
                ((unsigned)(gx + 3 + dw) < WW) ? 1.f : 0.f);
        }
    }

    float2 af01 = {0.f, 0.f}, af23 = {0.f, 0.f};

    // dh = 0 (same row), dw = 1..4  => j = 5..8
    row_accum_h<5, CM>(As[ty], Bs[ty], cb, ac01, ac23, bc01, bc23, m01, m23, af01, af23);

    if (FULLH) {
#pragma unroll
        for (int dh = 1; dh <= RAD; dh++)
            row_accum_h<0, CM>(As[ty+dh], Bs[ty+dh], cb,
                               ac01, ac23, bc01, bc23, m01, m23, af01, af23);
    } else {
        int dhmax = HH - 1 - gy; if (dhmax > RAD) dhmax = RAD;
#pragma unroll 1
        for (int dh = 1; dh <= dhmax; dh++)
            row_accum_h<0, CM>(As[ty+dh], Bs[ty+dh], cb,
                               ac01, ac23, bc01, bc23, m01, m23, af01, af23);
    }
    return (af01.x + af01.y) + (af23.x + af23.y);
}

// ---------------------------------------------------------------------------
// Kernel 2: census-SAD over half-space offsets (dh>0, or dh==0 && dw>0);
// each unordered pair counted once, doubled in finalize. fp16 core.
// ---------------------------------------------------------------------------
__global__ __launch_bounds__(NTHREADS)
void census_kernel(const float* __restrict__ a_g,   // pattern_proj
                   const float* __restrict__ b_g)   // im
{
    __shared__ __align__(16) __half As[TH][TW];
    __shared__ __align__(16) __half Bs[TH][TW];

    int x0 = blockIdx.x * TILE_W;
    int y0 = blockIdx.y * BYT;
    const float* ap = a_g + (size_t)blockIdx.z * (HH * WW);
    const float* bp = b_g + (size_t)blockIdx.z * (HH * WW);
    int tid = threadIdx.y * BXT + threadIdx.x;

    for (int i = tid; i < TH * TW; i += NTHREADS) {
        int r = i / TW, c = i - r * TW;
        int gy = y0 + r;
        int gx = x0 + c - RAD;
        float av = 0.f, bv = 0.f;
        if (gy < HH && (unsigned)gx < WW) {
            int g = gy * WW + gx;
            av = ap[g];
            bv = bp[g];
        }
        As[r][c] = __float2half_rn(av);
        Bs[r][c] = __float2half_rn(bv);
    }
    __syncthreads();

    int tx = threadIdx.x, ty = threadIdx.y;
    int cb = PX * tx;            // halo col base (even -> 8B-aligned half ptr)
    int gx = x0 + cb;
    int gy = y0 + ty;

    bool cm = (blockIdx.x == 0) || (blockIdx.x == gridDim.x - 1);
    bool fullh = (blockIdx.y != gridDim.y - 1);

    float acc;
    if (fullh) {
        acc = cm ? census_block_h<true , true >(As, Bs, gx, gy, ty, cb)
                 : census_block_h<false, true >(As, Bs, gx, gy, ty, cb);
    } else {
        acc = cm ? census_block_h<true , false>(As, Bs, gx, gy, ty, cb)
                 : census_block_h<false, false>(As, Bs, gx, gy, ty, cb);
    }

    // block reduce -> one double atomic per block
#pragma unroll
    for (int o = 16; o > 0; o >>= 1)
        acc += __shfl_down_sync(0xffffffffu, acc, o);

    __shared__ float warpsum[NTHREADS / 32];
    if ((tid & 31) == 0) warpsum[tid >> 5] = acc;
    __syncthreads();
    if (tid < (NTHREADS / 32)) {
        float s = warpsum[tid];
#pragma unroll
        for (int o = (NTHREADS / 64); o > 0; o >>= 1)
            s += __shfl_down_sync(0xffffffffu, s, o);
        if (tid == 0) atomicAdd(&g_acc, (double)s);
    }
}

// ---------------------------------------------------------------------------
// Kernel 3: val = 2 * g_acc / (81 * B*H*W)
// ---------------------------------------------------------------------------
__global__ void finalize_kernel(float* __restrict__ out, int lead, double inv_norm)
{
    float v = (float)(2.0 * g_acc * inv_norm);
    for (int i = threadIdx.x; i < lead; i += 32) out[i] = v;
}

extern "C" void kernel_launch(void* const* d_in, const int* in_sizes, int n_in,
                              void* d_out, int out_size)
{
    const float* disp    = (const float*)d_in[0];
    const float* im      = (const float*)d_in[1];
    const float* pattern = (const float*)d_in[2];
    float* out = (float*)d_out;

    int total = in_sizes[0];           // B*1*H*W
    int B = total / (HH * WW);
    int lead = out_size - total;       // scalar(s) precede pattern_proj
    float* proj = out + lead;

    dim3 pgrid(HH, B);
    proj_kernel<<<pgrid, PT>>>(disp, pattern, proj);

    dim3 grid(WW / TILE_W, HH / BYT, B);   // 5 x 64 x B
    dim3 blk(BXT, BYT);
    census_kernel<<<grid, blk>>>(proj, im);

    finalize_kernel<<<1, 32>>>(out, lead, 1.0 / (81.0 * (double)total));
}